// round 2
// baseline (speedup 1.0000x reference)
#include <cuda_runtime.h>
#include <cstdint>

// Problem constants
#define B_SZ 4
#define N_SEQ 2048
#define D_MODEL 1024
#define N_HEADS 16
#define HEAD_DIM 64
#define BH (B_SZ * N_HEADS)          // 64
#define TOKENS (B_SZ * N_SEQ)        // 8192
#define QKV_COLS (3 * D_MODEL)       // 3072

// Scratch (module-static device memory; no runtime allocation)
__device__ float g_qkv[3ull * BH * N_SEQ * HEAD_DIM];   // [sel][bh][n][dh]
__device__ float g_att[(size_t)TOKENS * D_MODEL];       // [b][n][h][dh] row-major tokens x 1024

// ---------------------------------------------------------------------------
// Tiled SGEMM: C[M,N] = A[M,K] @ B[K,N] + bias[N]
// mode 0: scatter epilogue into g_qkv ([sel][bh][n][dh])
// mode 1: plain write into C
// BM=BN=128, BK=8, TM=TN=8, 256 threads
// ---------------------------------------------------------------------------
#define BM 128
#define BN 128
#define BK 8
#define TM 8
#define TN 8

__global__ void __launch_bounds__(256, 2)
gemm_kernel(const float* __restrict__ A, const float* __restrict__ Bm,
            const float* __restrict__ bias, float* __restrict__ C,
            int M, int N, int K, int mode)
{
    __shared__ float As[BK][BM];
    __shared__ float Bs[BK][BN];

    const int tid  = threadIdx.x;
    const int crow = tid >> 4;          // 0..15
    const int ccol = tid & 15;          // 0..15
    const int arow = tid >> 1;          // 0..127
    const int acol = (tid & 1) << 2;    // 0 or 4
    const int brow = tid >> 5;          // 0..7
    const int bcol = (tid & 31) << 2;   // 0..124

    const float* Ap = A + (size_t)blockIdx.y * BM * K;
    const float* Bp = Bm + (size_t)blockIdx.x * BN;

    float acc[TM][TN];
#pragma unroll
    for (int i = 0; i < TM; i++)
#pragma unroll
        for (int j = 0; j < TN; j++) acc[i][j] = 0.f;

    for (int k0 = 0; k0 < K; k0 += BK) {
        float4 a4 = *(const float4*)(Ap + (size_t)arow * K + k0 + acol);
        As[acol + 0][arow] = a4.x;
        As[acol + 1][arow] = a4.y;
        As[acol + 2][arow] = a4.z;
        As[acol + 3][arow] = a4.w;
        *(float4*)(&Bs[brow][bcol]) =
            *(const float4*)(Bp + (size_t)(k0 + brow) * N + bcol);
        __syncthreads();

#pragma unroll
        for (int k = 0; k < BK; k++) {
            float ar[TM], br[TN];
#pragma unroll
            for (int i = 0; i < TM; i += 4)
                *(float4*)&ar[i] = *(float4*)&As[k][crow * TM + i];
#pragma unroll
            for (int j = 0; j < TN; j += 4)
                *(float4*)&br[j] = *(float4*)&Bs[k][ccol * TN + j];
#pragma unroll
            for (int i = 0; i < TM; i++)
#pragma unroll
                for (int j = 0; j < TN; j++)
                    acc[i][j] += ar[i] * br[j];
        }
        __syncthreads();
    }

    const int row0 = blockIdx.y * BM + crow * TM;
    const int col0 = blockIdx.x * BN + ccol * TN;

    if (mode == 0) {
        // scatter into g_qkv: col j -> sel = j/1024, h = (j/64)%16, dh = j%64
#pragma unroll
        for (int i = 0; i < TM; i++) {
            const int m = row0 + i;
            const int b = m >> 11;          // /2048
            const int n = m & 2047;
#pragma unroll
            for (int j = 0; j < TN; j++) {
                const int jg  = col0 + j;
                const int sel = jg >> 10;
                const int hh  = (jg >> 6) & 15;
                const int dh  = jg & 63;
                const float v = acc[i][j] + bias[jg];
                g_qkv[((size_t)(sel * BH + (b * N_HEADS + hh)) * N_SEQ + n) * HEAD_DIM + dh] = v;
            }
        }
    } else {
#pragma unroll
        for (int i = 0; i < TM; i++) {
            float* crow_ptr = C + (size_t)(row0 + i) * N + col0;
#pragma unroll
            for (int j = 0; j < TN; j++)
                crow_ptr[j] = acc[i][j] + bias[col0 + j];
        }
    }
}

// ---------------------------------------------------------------------------
// Flash attention: one CTA per (bh, 64-query tile). Br=Bc=64, d=64.
// 256 threads as a 16x16 grid, 4x4 micro-tiles. Online softmax.
// Dynamic smem: Qt[64][68] (transposed, pre-scaled), Kt[64][68] (transposed),
//               Vs[64][68], Ps[64][68]  -> 69632 bytes
// ---------------------------------------------------------------------------
#define APITCH 68
#define AT_SMEM_FLOATS (4 * 64 * APITCH)
#define AT_SMEM_BYTES (AT_SMEM_FLOATS * 4)

__global__ void __launch_bounds__(256, 2)
attn_kernel()
{
    extern __shared__ float sm[];
    float (*Qt)[APITCH] = (float(*)[APITCH])(sm);
    float (*Kt)[APITCH] = (float(*)[APITCH])(sm + 64 * APITCH);
    float (*Vs)[APITCH] = (float(*)[APITCH])(sm + 2 * 64 * APITCH);
    float (*Ps)[APITCH] = (float(*)[APITCH])(sm + 3 * 64 * APITCH);

    const int tid = threadIdx.x;
    const int ty = tid >> 4;   // 0..15 -> S rows ty*4..+3
    const int tx = tid & 15;   // 0..15 -> S cols tx*4..+3
    const int bh = blockIdx.y;
    const int qt = blockIdx.x;

    const float* Qg = g_qkv + ((size_t)(0 * BH + bh) * N_SEQ + qt * 64) * HEAD_DIM;
    const float* Kg0 = g_qkv + (size_t)(1 * BH + bh) * N_SEQ * HEAD_DIM;
    const float* Vg0 = g_qkv + (size_t)(2 * BH + bh) * N_SEQ * HEAD_DIM;

    const float SCALE = 0.125f;  // 1/sqrt(64)

    // Load Q tile, transposed + pre-scaled
#pragma unroll
    for (int it = 0; it < 4; it++) {
        int f = it * 256 + tid;        // float4 index 0..1023
        int r = f >> 4;
        int c4 = (f & 15) << 2;
        float4 v = *(const float4*)(Qg + r * HEAD_DIM + c4);
        Qt[c4 + 0][r] = v.x * SCALE;
        Qt[c4 + 1][r] = v.y * SCALE;
        Qt[c4 + 2][r] = v.z * SCALE;
        Qt[c4 + 3][r] = v.w * SCALE;
    }

    float m_r[4], l_r[4], o[4][4];
#pragma unroll
    for (int i = 0; i < 4; i++) {
        m_r[i] = -1e30f;
        l_r[i] = 0.f;
#pragma unroll
        for (int j = 0; j < 4; j++) o[i][j] = 0.f;
    }

    for (int kt = 0; kt < N_SEQ / 64; kt++) {
        const float* Kg = Kg0 + (size_t)kt * 64 * HEAD_DIM;
        const float* Vg = Vg0 + (size_t)kt * 64 * HEAD_DIM;
        // Load K (transposed) and V (direct)
#pragma unroll
        for (int it = 0; it < 4; it++) {
            int f = it * 256 + tid;
            int r = f >> 4;
            int c4 = (f & 15) << 2;
            float4 kv = *(const float4*)(Kg + r * HEAD_DIM + c4);
            Kt[c4 + 0][r] = kv.x;
            Kt[c4 + 1][r] = kv.y;
            Kt[c4 + 2][r] = kv.z;
            Kt[c4 + 3][r] = kv.w;
            *(float4*)&Vs[r][c4] = *(const float4*)(Vg + r * HEAD_DIM + c4);
        }
        __syncthreads();

        // S = Q @ K^T  (4x4 per thread)
        float s[4][4];
#pragma unroll
        for (int i = 0; i < 4; i++)
#pragma unroll
            for (int j = 0; j < 4; j++) s[i][j] = 0.f;

#pragma unroll 8
        for (int k = 0; k < 64; k++) {
            float4 a = *(float4*)&Qt[k][ty * 4];
            float4 b = *(float4*)&Kt[k][tx * 4];
            float ar[4] = {a.x, a.y, a.z, a.w};
            float br[4] = {b.x, b.y, b.z, b.w};
#pragma unroll
            for (int i = 0; i < 4; i++)
#pragma unroll
                for (int j = 0; j < 4; j++)
                    s[i][j] += ar[i] * br[j];
        }

        // Online softmax (row reductions across the 16 lanes sharing each row)
#pragma unroll
        for (int i = 0; i < 4; i++) {
            float mloc = fmaxf(fmaxf(s[i][0], s[i][1]), fmaxf(s[i][2], s[i][3]));
#pragma unroll
            for (int w = 1; w < 16; w <<= 1)
                mloc = fmaxf(mloc, __shfl_xor_sync(0xffffffffu, mloc, w));
            float mnew = fmaxf(m_r[i], mloc);
            float sc = __expf(m_r[i] - mnew);
            float lsum = 0.f;
#pragma unroll
            for (int j = 0; j < 4; j++) {
                float p = __expf(s[i][j] - mnew);
                s[i][j] = p;
                lsum += p;
            }
#pragma unroll
            for (int w = 1; w < 16; w <<= 1)
                lsum += __shfl_xor_sync(0xffffffffu, lsum, w);
            l_r[i] = l_r[i] * sc + lsum;
            m_r[i] = mnew;
#pragma unroll
            for (int j = 0; j < 4; j++) o[i][j] *= sc;
            *(float4*)&Ps[ty * 4 + i][tx * 4] = make_float4(s[i][0], s[i][1], s[i][2], s[i][3]);
        }
        __syncthreads();

        // O += P @ V
#pragma unroll 8
        for (int c = 0; c < 64; c++) {
            float4 v = *(float4*)&Vs[c][tx * 4];
            float vr[4] = {v.x, v.y, v.z, v.w};
#pragma unroll
            for (int i = 0; i < 4; i++) {
                float p = Ps[ty * 4 + i][c];
#pragma unroll
                for (int j = 0; j < 4; j++)
                    o[i][j] += p * vr[j];
            }
        }
        __syncthreads();
    }

    // Epilogue: normalize and write to g_att in [B,N,H,Dh] layout
    const int b = bh >> 4;
    const int h = bh & 15;
#pragma unroll
    for (int i = 0; i < 4; i++) {
        float inv_l = 1.0f / l_r[i];
        int qrow = qt * 64 + ty * 4 + i;
        float4 v = make_float4(o[i][0] * inv_l, o[i][1] * inv_l,
                               o[i][2] * inv_l, o[i][3] * inv_l);
        *(float4*)(g_att + ((size_t)(b * N_SEQ + qrow) * N_HEADS + h) * HEAD_DIM + tx * 4) = v;
    }
}

// ---------------------------------------------------------------------------
// Launch
// ---------------------------------------------------------------------------
extern "C" void kernel_launch(void* const* d_in, const int* in_sizes, int n_in,
                              void* d_out, int out_size)
{
    const float* x      = (const float*)d_in[0];
    const float* W_qkv  = (const float*)d_in[1];
    const float* b_qkv  = (const float*)d_in[2];
    const float* W_out  = (const float*)d_in[3];
    const float* b_out  = (const float*)d_in[4];
    float* out = (float*)d_out;

    float* g_att_ptr = nullptr;
    cudaGetSymbolAddress((void**)&g_att_ptr, g_att);

    // 1) QKV projection with scatter epilogue
    {
        dim3 grid(QKV_COLS / BN, TOKENS / BM);
        gemm_kernel<<<grid, 256>>>(x, W_qkv, b_qkv, nullptr,
                                   TOKENS, QKV_COLS, D_MODEL, 0);
    }

    // 2) Flash attention
    {
        static bool attr_set = false;
        if (!attr_set) {
            cudaFuncSetAttribute(attn_kernel,
                                 cudaFuncAttributeMaxDynamicSharedMemorySize,
                                 AT_SMEM_BYTES);
            attr_set = true;
        }
        dim3 grid(N_SEQ / 64, BH);
        attn_kernel<<<grid, 256, AT_SMEM_BYTES>>>();
    }

    // 3) Output projection
    {
        dim3 grid(D_MODEL / BN, TOKENS / BM);
        gemm_kernel<<<grid, 256>>>(g_att_ptr, W_out, b_out, out,
                                   TOKENS, D_MODEL, D_MODEL, 1);
    }
}

// round 3
// speedup vs baseline: 1.0005x; 1.0005x over previous
#include <cuda_runtime.h>
#include <cstdint>

// Problem constants
#define B_SZ 4
#define N_SEQ 2048
#define D_MODEL 1024
#define N_HEADS 16
#define HEAD_DIM 64
#define BH (B_SZ * N_HEADS)          // 64
#define TOKENS (B_SZ * N_SEQ)        // 8192
#define QKV_COLS (3 * D_MODEL)       // 3072

// Scratch (module-static device memory; no runtime allocation)
__device__ float g_qkv[3ull * BH * N_SEQ * HEAD_DIM];   // [sel][bh][n][dh]
__device__ float g_att[(size_t)TOKENS * D_MODEL];       // [b][n][h][dh] row-major tokens x 1024

// ---------------------------------------------------------------------------
// Tiled SGEMM: C[M,N] = A[M,K] @ B[K,N] + bias[N]
// mode 0: scatter epilogue into g_qkv ([sel][bh][n][dh])
// mode 1: plain write into C
// BM=BN=128, BK=8, TM=TN=8, 256 threads
// ---------------------------------------------------------------------------
#define BM 128
#define BN 128
#define BK 8
#define TM 8
#define TN 8

__global__ void __launch_bounds__(256, 2)
gemm_kernel(const float* __restrict__ A, const float* __restrict__ Bm,
            const float* __restrict__ bias, float* __restrict__ C,
            int M, int N, int K, int mode)
{
    __shared__ float As[BK][BM];
    __shared__ float Bs[BK][BN];

    const int tid  = threadIdx.x;
    const int crow = tid >> 4;          // 0..15
    const int ccol = tid & 15;          // 0..15
    const int arow = tid >> 1;          // 0..127
    const int acol = (tid & 1) << 2;    // 0 or 4
    const int brow = tid >> 5;          // 0..7
    const int bcol = (tid & 31) << 2;   // 0..124

    const float* Ap = A + (size_t)blockIdx.y * BM * K;
    const float* Bp = Bm + (size_t)blockIdx.x * BN;

    float acc[TM][TN];
#pragma unroll
    for (int i = 0; i < TM; i++)
#pragma unroll
        for (int j = 0; j < TN; j++) acc[i][j] = 0.f;

    for (int k0 = 0; k0 < K; k0 += BK) {
        float4 a4 = *(const float4*)(Ap + (size_t)arow * K + k0 + acol);
        As[acol + 0][arow] = a4.x;
        As[acol + 1][arow] = a4.y;
        As[acol + 2][arow] = a4.z;
        As[acol + 3][arow] = a4.w;
        *(float4*)(&Bs[brow][bcol]) =
            *(const float4*)(Bp + (size_t)(k0 + brow) * N + bcol);
        __syncthreads();

#pragma unroll
        for (int k = 0; k < BK; k++) {
            float ar[TM], br[TN];
#pragma unroll
            for (int i = 0; i < TM; i += 4)
                *(float4*)&ar[i] = *(float4*)&As[k][crow * TM + i];
#pragma unroll
            for (int j = 0; j < TN; j += 4)
                *(float4*)&br[j] = *(float4*)&Bs[k][ccol * TN + j];
#pragma unroll
            for (int i = 0; i < TM; i++)
#pragma unroll
                for (int j = 0; j < TN; j++)
                    acc[i][j] += ar[i] * br[j];
        }
        __syncthreads();
    }

    const int row0 = blockIdx.y * BM + crow * TM;
    const int col0 = blockIdx.x * BN + ccol * TN;

    if (mode == 0) {
        // scatter into g_qkv: col j -> sel = j/1024, h = (j/64)%16, dh = j%64
#pragma unroll
        for (int i = 0; i < TM; i++) {
            const int m = row0 + i;
            const int b = m >> 11;          // /2048
            const int n = m & 2047;
#pragma unroll
            for (int j = 0; j < TN; j++) {
                const int jg  = col0 + j;
                const int sel = jg >> 10;
                const int hh  = (jg >> 6) & 15;
                const int dh  = jg & 63;
                const float v = acc[i][j] + bias[jg];
                g_qkv[((size_t)(sel * BH + (b * N_HEADS + hh)) * N_SEQ + n) * HEAD_DIM + dh] = v;
            }
        }
    } else {
#pragma unroll
        for (int i = 0; i < TM; i++) {
            float* crow_ptr = C + (size_t)(row0 + i) * N + col0;
#pragma unroll
            for (int j = 0; j < TN; j++)
                crow_ptr[j] = acc[i][j] + bias[col0 + j];
        }
    }
}

// ---------------------------------------------------------------------------
// Flash attention: one CTA per (bh, 64-query tile). Br=Bc=64, d=64.
// 256 threads as a 16x16 grid, 4x4 micro-tiles. Online softmax.
// Dynamic smem: Qt[64][68] (transposed, pre-scaled), Kt[64][68] (transposed),
//               Vs[64][68], Ps[64][68]  -> 69632 bytes
// ---------------------------------------------------------------------------
#define APITCH 68
#define AT_SMEM_FLOATS (4 * 64 * APITCH)
#define AT_SMEM_BYTES (AT_SMEM_FLOATS * 4)

__global__ void __launch_bounds__(256, 2)
attn_kernel()
{
    extern __shared__ float sm[];
    float (*Qt)[APITCH] = (float(*)[APITCH])(sm);
    float (*Kt)[APITCH] = (float(*)[APITCH])(sm + 64 * APITCH);
    float (*Vs)[APITCH] = (float(*)[APITCH])(sm + 2 * 64 * APITCH);
    float (*Ps)[APITCH] = (float(*)[APITCH])(sm + 3 * 64 * APITCH);

    const int tid = threadIdx.x;
    const int ty = tid >> 4;   // 0..15 -> S rows ty*4..+3
    const int tx = tid & 15;   // 0..15 -> S cols tx*4..+3
    const int bh = blockIdx.y;
    const int qt = blockIdx.x;

    const float* Qg = g_qkv + ((size_t)(0 * BH + bh) * N_SEQ + qt * 64) * HEAD_DIM;
    const float* Kg0 = g_qkv + (size_t)(1 * BH + bh) * N_SEQ * HEAD_DIM;
    const float* Vg0 = g_qkv + (size_t)(2 * BH + bh) * N_SEQ * HEAD_DIM;

    const float SCALE = 0.125f;  // 1/sqrt(64)

    // Load Q tile, transposed + pre-scaled
#pragma unroll
    for (int it = 0; it < 4; it++) {
        int f = it * 256 + tid;        // float4 index 0..1023
        int r = f >> 4;
        int c4 = (f & 15) << 2;
        float4 v = *(const float4*)(Qg + r * HEAD_DIM + c4);
        Qt[c4 + 0][r] = v.x * SCALE;
        Qt[c4 + 1][r] = v.y * SCALE;
        Qt[c4 + 2][r] = v.z * SCALE;
        Qt[c4 + 3][r] = v.w * SCALE;
    }

    float m_r[4], l_r[4], o[4][4];
#pragma unroll
    for (int i = 0; i < 4; i++) {
        m_r[i] = -1e30f;
        l_r[i] = 0.f;
#pragma unroll
        for (int j = 0; j < 4; j++) o[i][j] = 0.f;
    }

    for (int kt = 0; kt < N_SEQ / 64; kt++) {
        const float* Kg = Kg0 + (size_t)kt * 64 * HEAD_DIM;
        const float* Vg = Vg0 + (size_t)kt * 64 * HEAD_DIM;
        // Load K (transposed) and V (direct)
#pragma unroll
        for (int it = 0; it < 4; it++) {
            int f = it * 256 + tid;
            int r = f >> 4;
            int c4 = (f & 15) << 2;
            float4 kv = *(const float4*)(Kg + r * HEAD_DIM + c4);
            Kt[c4 + 0][r] = kv.x;
            Kt[c4 + 1][r] = kv.y;
            Kt[c4 + 2][r] = kv.z;
            Kt[c4 + 3][r] = kv.w;
            *(float4*)&Vs[r][c4] = *(const float4*)(Vg + r * HEAD_DIM + c4);
        }
        __syncthreads();

        // S = Q @ K^T  (4x4 per thread)
        float s[4][4];
#pragma unroll
        for (int i = 0; i < 4; i++)
#pragma unroll
            for (int j = 0; j < 4; j++) s[i][j] = 0.f;

#pragma unroll 8
        for (int k = 0; k < 64; k++) {
            float4 a = *(float4*)&Qt[k][ty * 4];
            float4 b = *(float4*)&Kt[k][tx * 4];
            float ar[4] = {a.x, a.y, a.z, a.w};
            float br[4] = {b.x, b.y, b.z, b.w};
#pragma unroll
            for (int i = 0; i < 4; i++)
#pragma unroll
                for (int j = 0; j < 4; j++)
                    s[i][j] += ar[i] * br[j];
        }

        // Online softmax (row reductions across the 16 lanes sharing each row)
#pragma unroll
        for (int i = 0; i < 4; i++) {
            float mloc = fmaxf(fmaxf(s[i][0], s[i][1]), fmaxf(s[i][2], s[i][3]));
#pragma unroll
            for (int w = 1; w < 16; w <<= 1)
                mloc = fmaxf(mloc, __shfl_xor_sync(0xffffffffu, mloc, w));
            float mnew = fmaxf(m_r[i], mloc);
            float sc = __expf(m_r[i] - mnew);
            float lsum = 0.f;
#pragma unroll
            for (int j = 0; j < 4; j++) {
                float p = __expf(s[i][j] - mnew);
                s[i][j] = p;
                lsum += p;
            }
#pragma unroll
            for (int w = 1; w < 16; w <<= 1)
                lsum += __shfl_xor_sync(0xffffffffu, lsum, w);
            l_r[i] = l_r[i] * sc + lsum;
            m_r[i] = mnew;
#pragma unroll
            for (int j = 0; j < 4; j++) o[i][j] *= sc;
            *(float4*)&Ps[ty * 4 + i][tx * 4] = make_float4(s[i][0], s[i][1], s[i][2], s[i][3]);
        }
        __syncthreads();

        // O += P @ V
#pragma unroll 8
        for (int c = 0; c < 64; c++) {
            float4 v = *(float4*)&Vs[c][tx * 4];
            float vr[4] = {v.x, v.y, v.z, v.w};
#pragma unroll
            for (int i = 0; i < 4; i++) {
                float p = Ps[ty * 4 + i][c];
#pragma unroll
                for (int j = 0; j < 4; j++)
                    o[i][j] += p * vr[j];
            }
        }
        __syncthreads();
    }

    // Epilogue: normalize and write to g_att in [B,N,H,Dh] layout
    const int b = bh >> 4;
    const int h = bh & 15;
#pragma unroll
    for (int i = 0; i < 4; i++) {
        float inv_l = 1.0f / l_r[i];
        int qrow = qt * 64 + ty * 4 + i;
        float4 v = make_float4(o[i][0] * inv_l, o[i][1] * inv_l,
                               o[i][2] * inv_l, o[i][3] * inv_l);
        *(float4*)(g_att + ((size_t)(b * N_SEQ + qrow) * N_HEADS + h) * HEAD_DIM + tx * 4) = v;
    }
}

// ---------------------------------------------------------------------------
// Launch
// ---------------------------------------------------------------------------
extern "C" void kernel_launch(void* const* d_in, const int* in_sizes, int n_in,
                              void* d_out, int out_size)
{
    const float* x      = (const float*)d_in[0];
    const float* W_qkv  = (const float*)d_in[1];
    const float* b_qkv  = (const float*)d_in[2];
    const float* W_out  = (const float*)d_in[3];
    const float* b_out  = (const float*)d_in[4];
    float* out = (float*)d_out;

    float* g_att_ptr = nullptr;
    cudaGetSymbolAddress((void**)&g_att_ptr, g_att);

    // 1) QKV projection with scatter epilogue
    {
        dim3 grid(QKV_COLS / BN, TOKENS / BM);
        gemm_kernel<<<grid, 256>>>(x, W_qkv, b_qkv, nullptr,
                                   TOKENS, QKV_COLS, D_MODEL, 0);
    }

    // 2) Flash attention
    {
        static bool attr_set = false;
        if (!attr_set) {
            cudaFuncSetAttribute(attn_kernel,
                                 cudaFuncAttributeMaxDynamicSharedMemorySize,
                                 AT_SMEM_BYTES);
            attr_set = true;
        }
        dim3 grid(N_SEQ / 64, BH);
        attn_kernel<<<grid, 256, AT_SMEM_BYTES>>>();
    }

    // 3) Output projection
    {
        dim3 grid(D_MODEL / BN, TOKENS / BM);
        gemm_kernel<<<grid, 256>>>(g_att_ptr, W_out, b_out, out,
                                   TOKENS, D_MODEL, D_MODEL, 1);
    }
}

// round 4
// speedup vs baseline: 1.0009x; 1.0004x over previous
#include <cuda_runtime.h>
#include <cstdint>

// Problem constants
#define B_SZ 4
#define N_SEQ 2048
#define D_MODEL 1024
#define N_HEADS 16
#define HEAD_DIM 64
#define BH (B_SZ * N_HEADS)          // 64
#define TOKENS (B_SZ * N_SEQ)        // 8192
#define QKV_COLS (3 * D_MODEL)       // 3072

// Scratch (module-static device memory; no runtime allocation)
__device__ float g_qkv[3ull * BH * N_SEQ * HEAD_DIM];   // [sel][bh][n][dh]
__device__ float g_att[(size_t)TOKENS * D_MODEL];       // [b][n][h][dh] row-major tokens x 1024

// ---------------------------------------------------------------------------
// Tiled SGEMM: C[M,N] = A[M,K] @ B[K,N] + bias[N]
// mode 0: scatter epilogue into g_qkv ([sel][bh][n][dh])
// mode 1: plain write into C
// BM=BN=128, BK=8, TM=TN=8, 256 threads
// ---------------------------------------------------------------------------
#define BM 128
#define BN 128
#define BK 8
#define TM 8
#define TN 8

__global__ void __launch_bounds__(256, 2)
gemm_kernel(const float* __restrict__ A, const float* __restrict__ Bm,
            const float* __restrict__ bias, float* __restrict__ C,
            int M, int N, int K, int mode)
{
    __shared__ float As[BK][BM];
    __shared__ float Bs[BK][BN];

    const int tid  = threadIdx.x;
    const int crow = tid >> 4;          // 0..15
    const int ccol = tid & 15;          // 0..15
    const int arow = tid >> 1;          // 0..127
    const int acol = (tid & 1) << 2;    // 0 or 4
    const int brow = tid >> 5;          // 0..7
    const int bcol = (tid & 31) << 2;   // 0..124

    const float* Ap = A + (size_t)blockIdx.y * BM * K;
    const float* Bp = Bm + (size_t)blockIdx.x * BN;

    float acc[TM][TN];
#pragma unroll
    for (int i = 0; i < TM; i++)
#pragma unroll
        for (int j = 0; j < TN; j++) acc[i][j] = 0.f;

    for (int k0 = 0; k0 < K; k0 += BK) {
        float4 a4 = *(const float4*)(Ap + (size_t)arow * K + k0 + acol);
        As[acol + 0][arow] = a4.x;
        As[acol + 1][arow] = a4.y;
        As[acol + 2][arow] = a4.z;
        As[acol + 3][arow] = a4.w;
        *(float4*)(&Bs[brow][bcol]) =
            *(const float4*)(Bp + (size_t)(k0 + brow) * N + bcol);
        __syncthreads();

#pragma unroll
        for (int k = 0; k < BK; k++) {
            float ar[TM], br[TN];
#pragma unroll
            for (int i = 0; i < TM; i += 4)
                *(float4*)&ar[i] = *(float4*)&As[k][crow * TM + i];
#pragma unroll
            for (int j = 0; j < TN; j += 4)
                *(float4*)&br[j] = *(float4*)&Bs[k][ccol * TN + j];
#pragma unroll
            for (int i = 0; i < TM; i++)
#pragma unroll
                for (int j = 0; j < TN; j++)
                    acc[i][j] += ar[i] * br[j];
        }
        __syncthreads();
    }

    const int row0 = blockIdx.y * BM + crow * TM;
    const int col0 = blockIdx.x * BN + ccol * TN;

    if (mode == 0) {
        // scatter into g_qkv: col j -> sel = j/1024, h = (j/64)%16, dh = j%64
#pragma unroll
        for (int i = 0; i < TM; i++) {
            const int m = row0 + i;
            const int b = m >> 11;          // /2048
            const int n = m & 2047;
#pragma unroll
            for (int j = 0; j < TN; j++) {
                const int jg  = col0 + j;
                const int sel = jg >> 10;
                const int hh  = (jg >> 6) & 15;
                const int dh  = jg & 63;
                const float v = acc[i][j] + bias[jg];
                g_qkv[((size_t)(sel * BH + (b * N_HEADS + hh)) * N_SEQ + n) * HEAD_DIM + dh] = v;
            }
        }
    } else {
#pragma unroll
        for (int i = 0; i < TM; i++) {
            float* crow_ptr = C + (size_t)(row0 + i) * N + col0;
#pragma unroll
            for (int j = 0; j < TN; j++)
                crow_ptr[j] = acc[i][j] + bias[col0 + j];
        }
    }
}

// ---------------------------------------------------------------------------
// Flash attention: one CTA per (bh, 64-query tile). Br=Bc=64, d=64.
// 256 threads as a 16x16 grid, 4x4 micro-tiles. Online softmax.
// Dynamic smem: Qt[64][68] (transposed, pre-scaled), Kt[64][68] (transposed),
//               Vs[64][68], Ps[64][68]  -> 69632 bytes
// ---------------------------------------------------------------------------
#define APITCH 68
#define AT_SMEM_FLOATS (4 * 64 * APITCH)
#define AT_SMEM_BYTES (AT_SMEM_FLOATS * 4)

__global__ void __launch_bounds__(256, 2)
attn_kernel()
{
    extern __shared__ float sm[];
    float (*Qt)[APITCH] = (float(*)[APITCH])(sm);
    float (*Kt)[APITCH] = (float(*)[APITCH])(sm + 64 * APITCH);
    float (*Vs)[APITCH] = (float(*)[APITCH])(sm + 2 * 64 * APITCH);
    float (*Ps)[APITCH] = (float(*)[APITCH])(sm + 3 * 64 * APITCH);

    const int tid = threadIdx.x;
    const int ty = tid >> 4;   // 0..15 -> S rows ty*4..+3
    const int tx = tid & 15;   // 0..15 -> S cols tx*4..+3
    const int bh = blockIdx.y;
    const int qt = blockIdx.x;

    const float* Qg = g_qkv + ((size_t)(0 * BH + bh) * N_SEQ + qt * 64) * HEAD_DIM;
    const float* Kg0 = g_qkv + (size_t)(1 * BH + bh) * N_SEQ * HEAD_DIM;
    const float* Vg0 = g_qkv + (size_t)(2 * BH + bh) * N_SEQ * HEAD_DIM;

    const float SCALE = 0.125f;  // 1/sqrt(64)

    // Load Q tile, transposed + pre-scaled
#pragma unroll
    for (int it = 0; it < 4; it++) {
        int f = it * 256 + tid;        // float4 index 0..1023
        int r = f >> 4;
        int c4 = (f & 15) << 2;
        float4 v = *(const float4*)(Qg + r * HEAD_DIM + c4);
        Qt[c4 + 0][r] = v.x * SCALE;
        Qt[c4 + 1][r] = v.y * SCALE;
        Qt[c4 + 2][r] = v.z * SCALE;
        Qt[c4 + 3][r] = v.w * SCALE;
    }

    float m_r[4], l_r[4], o[4][4];
#pragma unroll
    for (int i = 0; i < 4; i++) {
        m_r[i] = -1e30f;
        l_r[i] = 0.f;
#pragma unroll
        for (int j = 0; j < 4; j++) o[i][j] = 0.f;
    }

    for (int kt = 0; kt < N_SEQ / 64; kt++) {
        const float* Kg = Kg0 + (size_t)kt * 64 * HEAD_DIM;
        const float* Vg = Vg0 + (size_t)kt * 64 * HEAD_DIM;
        // Load K (transposed) and V (direct)
#pragma unroll
        for (int it = 0; it < 4; it++) {
            int f = it * 256 + tid;
            int r = f >> 4;
            int c4 = (f & 15) << 2;
            float4 kv = *(const float4*)(Kg + r * HEAD_DIM + c4);
            Kt[c4 + 0][r] = kv.x;
            Kt[c4 + 1][r] = kv.y;
            Kt[c4 + 2][r] = kv.z;
            Kt[c4 + 3][r] = kv.w;
            *(float4*)&Vs[r][c4] = *(const float4*)(Vg + r * HEAD_DIM + c4);
        }
        __syncthreads();

        // S = Q @ K^T  (4x4 per thread)
        float s[4][4];
#pragma unroll
        for (int i = 0; i < 4; i++)
#pragma unroll
            for (int j = 0; j < 4; j++) s[i][j] = 0.f;

#pragma unroll 8
        for (int k = 0; k < 64; k++) {
            float4 a = *(float4*)&Qt[k][ty * 4];
            float4 b = *(float4*)&Kt[k][tx * 4];
            float ar[4] = {a.x, a.y, a.z, a.w};
            float br[4] = {b.x, b.y, b.z, b.w};
#pragma unroll
            for (int i = 0; i < 4; i++)
#pragma unroll
                for (int j = 0; j < 4; j++)
                    s[i][j] += ar[i] * br[j];
        }

        // Online softmax (row reductions across the 16 lanes sharing each row)
#pragma unroll
        for (int i = 0; i < 4; i++) {
            float mloc = fmaxf(fmaxf(s[i][0], s[i][1]), fmaxf(s[i][2], s[i][3]));
#pragma unroll
            for (int w = 1; w < 16; w <<= 1)
                mloc = fmaxf(mloc, __shfl_xor_sync(0xffffffffu, mloc, w));
            float mnew = fmaxf(m_r[i], mloc);
            float sc = __expf(m_r[i] - mnew);
            float lsum = 0.f;
#pragma unroll
            for (int j = 0; j < 4; j++) {
                float p = __expf(s[i][j] - mnew);
                s[i][j] = p;
                lsum += p;
            }
#pragma unroll
            for (int w = 1; w < 16; w <<= 1)
                lsum += __shfl_xor_sync(0xffffffffu, lsum, w);
            l_r[i] = l_r[i] * sc + lsum;
            m_r[i] = mnew;
#pragma unroll
            for (int j = 0; j < 4; j++) o[i][j] *= sc;
            *(float4*)&Ps[ty * 4 + i][tx * 4] = make_float4(s[i][0], s[i][1], s[i][2], s[i][3]);
        }
        __syncthreads();

        // O += P @ V
#pragma unroll 8
        for (int c = 0; c < 64; c++) {
            float4 v = *(float4*)&Vs[c][tx * 4];
            float vr[4] = {v.x, v.y, v.z, v.w};
#pragma unroll
            for (int i = 0; i < 4; i++) {
                float p = Ps[ty * 4 + i][c];
#pragma unroll
                for (int j = 0; j < 4; j++)
                    o[i][j] += p * vr[j];
            }
        }
        __syncthreads();
    }

    // Epilogue: normalize and write to g_att in [B,N,H,Dh] layout
    const int b = bh >> 4;
    const int h = bh & 15;
#pragma unroll
    for (int i = 0; i < 4; i++) {
        float inv_l = 1.0f / l_r[i];
        int qrow = qt * 64 + ty * 4 + i;
        float4 v = make_float4(o[i][0] * inv_l, o[i][1] * inv_l,
                               o[i][2] * inv_l, o[i][3] * inv_l);
        *(float4*)(g_att + ((size_t)(b * N_SEQ + qrow) * N_HEADS + h) * HEAD_DIM + tx * 4) = v;
    }
}

// ---------------------------------------------------------------------------
// Launch
// ---------------------------------------------------------------------------
extern "C" void kernel_launch(void* const* d_in, const int* in_sizes, int n_in,
                              void* d_out, int out_size)
{
    const float* x      = (const float*)d_in[0];
    const float* W_qkv  = (const float*)d_in[1];
    const float* b_qkv  = (const float*)d_in[2];
    const float* W_out  = (const float*)d_in[3];
    const float* b_out  = (const float*)d_in[4];
    float* out = (float*)d_out;

    float* g_att_ptr = nullptr;
    cudaGetSymbolAddress((void**)&g_att_ptr, g_att);

    // 1) QKV projection with scatter epilogue
    {
        dim3 grid(QKV_COLS / BN, TOKENS / BM);
        gemm_kernel<<<grid, 256>>>(x, W_qkv, b_qkv, nullptr,
                                   TOKENS, QKV_COLS, D_MODEL, 0);
    }

    // 2) Flash attention
    {
        static bool attr_set = false;
        if (!attr_set) {
            cudaFuncSetAttribute(attn_kernel,
                                 cudaFuncAttributeMaxDynamicSharedMemorySize,
                                 AT_SMEM_BYTES);
            attr_set = true;
        }
        dim3 grid(N_SEQ / 64, BH);
        attn_kernel<<<grid, 256, AT_SMEM_BYTES>>>();
    }

    // 3) Output projection
    {
        dim3 grid(D_MODEL / BN, TOKENS / BM);
        gemm_kernel<<<grid, 256>>>(g_att_ptr, W_out, b_out, out,
                                   TOKENS, D_MODEL, D_MODEL, 1);
    }
}